// round 13
// baseline (speedup 1.0000x reference)
#include <cuda_runtime.h>
#include <cuda_bf16.h>
#include <cstdint>

// ---------------------------------------------------------------------------
// SNN MLP forward — int8 3-split tensor-core edition (sm_80-era PTX only):
//   Xq = int8(X)                        (binary -> exact, prepacked A-frag order)
//   W1 = s*(65536*h + 256*m + l)        (balanced base-256 s8 digits, 23-bit)
//   U1 = s*(65536*H + 256*M + L)        H,M,L = Xq@h, Xq@m, Xq@l  (exact s32 mma)
//   S1 = LIF-scan(U1) + fused rare-spike scatter into U2 (replaces gemm2)
//   S2 = LIF-scan(U2) smem-staged
// NO tcgen05 / no 'a'-suffix features: harness ptxas target is compute_103.
// ---------------------------------------------------------------------------

#define T_STEPS  100
#define BATCH    256
#define IN_DIM   784
#define HID_DIM  1024
#define OUT_DIM  10
#define M_ROWS   25600
#define KP       832                 // 26 k32-tiles
#define KT_TILES 26
#define MT_TILES 1600                // M_ROWS/16
#define NT_TILES 128                 // HID_DIM/8
#define DECAY_F  0.6f
#define THRESH_F 0.9f
#define QLEV     8323072.0f          // 127*65536 + 127*256 + ... balanced 23-bit range

// GEMM tiling: BM=128 (8 m16), BN=64 (8 n8), BK=64 (2 k32/stage), 3 stages
#define NSTAGE_IT 13                 // 832/64
#define STAGE_BYTES 20480            // A 8KB + Bh 4KB + Bm 4KB + Bl 4KB
#define SA_OFF  0
#define SBH_OFF 8192
#define SBM_OFF 12288
#define SBL_OFF 16384
#define SMEM_GEMM (3 * STAGE_BYTES)  // 61440

// Device scratch
__device__ float g_u1[(size_t)M_ROWS * HID_DIM];      // 104 MB
__device__ float g_u2[(size_t)M_ROWS * OUT_DIM];      //   1 MB
__device__ float g_s1[(size_t)M_ROWS * HID_DIM];      // fallback hidden store
__device__ __align__(16) uint8_t g_xa[(size_t)KT_TILES * MT_TILES * 512];   // 21.3 MB
__device__ __align__(16) uint8_t g_wh[(size_t)KT_TILES * NT_TILES * 256];
__device__ __align__(16) uint8_t g_wm[(size_t)KT_TILES * NT_TILES * 256];
__device__ __align__(16) uint8_t g_wl[(size_t)KT_TILES * NT_TILES * 256];
__device__ unsigned int g_wmax;

// ---------------------------------------------------------------------------
// PTX helpers (sm_80-era)
// ---------------------------------------------------------------------------
__device__ __forceinline__ uint32_t smem_u32(const void* p) {
    uint32_t a;
    asm("{ .reg .u64 t; cvta.to.shared.u64 t, %1; cvt.u32.u64 %0, t; }" : "=r"(a) : "l"(p));
    return a;
}
__device__ __forceinline__ void cp16(uint32_t dst, const void* src) {
    asm volatile("cp.async.cg.shared.global [%0], [%1], 16;" :: "r"(dst), "l"(src));
}
__device__ __forceinline__ void cp_commit() { asm volatile("cp.async.commit_group;" ::: "memory"); }
__device__ __forceinline__ void cp_wait2()  { asm volatile("cp.async.wait_group 2;"  ::: "memory"); }

__device__ __forceinline__ void lds128(uint32_t* r, uint32_t a) {
    asm volatile("ld.shared.v4.u32 {%0,%1,%2,%3}, [%4];"
                 : "=r"(r[0]), "=r"(r[1]), "=r"(r[2]), "=r"(r[3]) : "r"(a));
}
__device__ __forceinline__ void lds64(uint32_t* r, uint32_t a) {
    asm volatile("ld.shared.v2.u32 {%0,%1}, [%2];" : "=r"(r[0]), "=r"(r[1]) : "r"(a));
}
__device__ __forceinline__ void mma_s8(int* c, const uint32_t* a, uint32_t b0, uint32_t b1) {
    asm volatile("mma.sync.aligned.m16n8k32.row.col.s32.s8.s8.s32 "
                 "{%0,%1,%2,%3}, {%4,%5,%6,%7}, {%8,%9}, {%0,%1,%2,%3};"
                 : "+r"(c[0]), "+r"(c[1]), "+r"(c[2]), "+r"(c[3])
                 : "r"(a[0]), "r"(a[1]), "r"(a[2]), "r"(a[3]), "r"(b0), "r"(b1));
}

// ---------------------------------------------------------------------------
// conv_x: X fp32 -> g_xa int8, prepacked per (kt,mt) tile in m16n8k32 A-frag order
// ---------------------------------------------------------------------------
__device__ __forceinline__ uint32_t pack_x4(const float* X, int r, int k)
{
    if (k >= IN_DIM) return 0u;                       // 784 = 49*16 -> clean boundary
    float4 v = *reinterpret_cast<const float4*>(X + (size_t)r * IN_DIM + k);
    uint32_t b0 = (v.x != 0.f), b1 = (v.y != 0.f), b2 = (v.z != 0.f), b3 = (v.w != 0.f);
    return b0 | (b1 << 8) | (b2 << 16) | (b3 << 24);
}

__global__ void conv_x_kernel(const float* __restrict__ X)
{
    int t = blockIdx.x * blockDim.x + threadIdx.x;
    if (t >= KT_TILES * MT_TILES * 32) return;
    int lane = t & 31;
    int tile = t >> 5;
    int kt = tile / MT_TILES;
    int mt = tile - kt * MT_TILES;

    int r  = mt * 16 + (lane >> 2);
    int kb = kt * 32 + 4 * (lane & 3);

    uint4 frag;
    frag.x = pack_x4(X, r,     kb);
    frag.y = pack_x4(X, r + 8, kb);
    frag.z = pack_x4(X, r,     kb + 16);
    frag.w = pack_x4(X, r + 8, kb + 16);
    *reinterpret_cast<uint4*>(&g_xa[(size_t)t * 16]) = frag;
}

// ---------------------------------------------------------------------------
// zero kernels (split in two so the GEMM lands on ncu launch slot 6)
// ---------------------------------------------------------------------------
#define U2Q (M_ROWS * OUT_DIM / 4)      // 64000 float4s
__global__ void zero_a_kernel()
{
    int idx = blockIdx.x * blockDim.x + threadIdx.x;
    if (idx < U2Q / 2)
        reinterpret_cast<float4*>(g_u2)[idx] = make_float4(0.f, 0.f, 0.f, 0.f);
    if (idx == 0) g_wmax = 0u;
}
__global__ void zero_b_kernel()
{
    int idx = blockIdx.x * blockDim.x + threadIdx.x;
    if (idx < U2Q - U2Q / 2)
        reinterpret_cast<float4*>(g_u2)[U2Q / 2 + idx] = make_float4(0.f, 0.f, 0.f, 0.f);
}

// ---------------------------------------------------------------------------
// wmax: max|W1| (atomicMax on positive-float bits)
// ---------------------------------------------------------------------------
__global__ void wmax_kernel(const float* __restrict__ W1)
{
    float m = 0.f;
    for (int i = blockIdx.x * blockDim.x + threadIdx.x;
         i < IN_DIM * HID_DIM; i += gridDim.x * blockDim.x)
        m = fmaxf(m, fabsf(W1[i]));
#pragma unroll
    for (int off = 16; off > 0; off >>= 1)
        m = fmaxf(m, __shfl_xor_sync(0xFFFFFFFFu, m, off));
    if ((threadIdx.x & 31) == 0)
        atomicMax(&g_wmax, __float_as_uint(m));
}

// ---------------------------------------------------------------------------
// conv_w: W1 -> 3 balanced base-256 s8 digit planes, prepacked B-frag order.
//   q = rn(w/s), |q| <= 8323072;  l,m,h in [-128,127];  q = 65536h + 256m + l
// ---------------------------------------------------------------------------
__device__ __forceinline__ void quant4_3(const float* W1, int k, int n, float inv_s,
                                         uint32_t& hb, uint32_t& mb, uint32_t& lb)
{
    hb = 0u; mb = 0u; lb = 0u;
#pragma unroll
    for (int j = 0; j < 4; j++) {
        int kk = k + j;
        float w = (kk < IN_DIM) ? W1[(size_t)kk * HID_DIM + n] : 0.f;
        int q  = __float2int_rn(w * inv_s);
        int l  = ((q + 128) & 255) - 128;
        int q1 = (q - l) >> 8;
        int m  = ((q1 + 128) & 255) - 128;
        int h  = (q1 - m) >> 8;
        hb |= (uint32_t)(h & 0xFF) << (8 * j);
        mb |= (uint32_t)(m & 0xFF) << (8 * j);
        lb |= (uint32_t)(l & 0xFF) << (8 * j);
    }
}

__global__ void conv_w_kernel(const float* __restrict__ W1)
{
    int t = blockIdx.x * blockDim.x + threadIdx.x;
    if (t >= KT_TILES * NT_TILES * 32) return;
    int lane = t & 31;
    int tile = t >> 5;
    int kt = tile >> 7;
    int nt = tile & 127;

    int n  = nt * 8 + (lane >> 2);
    int kb = kt * 32 + 4 * (lane & 3);
    float inv_s = QLEV / __uint_as_float(g_wmax);

    uint32_t h0, m0, l0, h1, m1, l1;
    quant4_3(W1, kb,      n, inv_s, h0, m0, l0);
    quant4_3(W1, kb + 16, n, inv_s, h1, m1, l1);
    *reinterpret_cast<uint2*>(&g_wh[(size_t)t * 8]) = make_uint2(h0, h1);
    *reinterpret_cast<uint2*>(&g_wm[(size_t)t * 8]) = make_uint2(m0, m1);
    *reinterpret_cast<uint2*>(&g_wl[(size_t)t * 8]) = make_uint2(l0, l1);
}

// ---------------------------------------------------------------------------
// GEMM1: U1 = s*(65536*H + 256*M + L), exact int mma, fp32 combine.
// 256 threads = 8 warps (4m x 2n), warp tile 32x32; BM=128, BN=64, BK=64;
// 3-stage cp.async; operands prepacked -> linear copies, no ldmatrix.
// ---------------------------------------------------------------------------
__global__ void __launch_bounds__(256, 1)
gemm1_i8_kernel()
{
    extern __shared__ char smem[];
    const uint32_t sb = smem_u32(smem);
    const int tid  = threadIdx.x;
    const int lane = tid & 31;
    const int w    = tid >> 5;
    const int wm   = w >> 1;           // 0..3  (m: 32 rows each)
    const int wn   = w & 1;            // 0..1  (n: 32 cols each)
    const int bx   = blockIdx.x;       // 0..15 (N tiles of 64)
    const int by   = blockIdx.y;       // 0..199

    const uint8_t* Abase = g_xa + (size_t)by * 8 * 512;
    const uint8_t* Hbase = g_wh + (size_t)bx * 8 * 256;
    const uint8_t* Mbase = g_wm + (size_t)bx * 8 * 256;
    const uint8_t* Lbase = g_wl + (size_t)bx * 8 * 256;

    // stage copy: A = 2 cp16/thread (8KB), each B plane = 1 cp16/thread (4KB)
    const int kb_ld  = tid >> 7;                 // B: ktl
    const int boff_ld = (tid & 127) * 16;        // B: within-kt 2KB (8 nt x 256B)
    auto load_stage = [&](int it, int s) {
        uint32_t st = sb + (uint32_t)s * STAGE_BYTES;
#pragma unroll
        for (int h = 0; h < 2; h++) {
            int id  = tid + h * 256;             // 0..511
            int ktl = id >> 8;
            int off = (id & 255) * 16;           // mt*512 + lane*16
            cp16(st + SA_OFF + (uint32_t)id * 16,
                 Abase + (size_t)(it * 2 + ktl) * (MT_TILES * 512) + off);
        }
        size_t kt = (size_t)(it * 2 + kb_ld) * (NT_TILES * 256);
        cp16(st + SBH_OFF + (uint32_t)tid * 16, Hbase + kt + boff_ld);
        cp16(st + SBM_OFF + (uint32_t)tid * 16, Mbase + kt + boff_ld);
        cp16(st + SBL_OFF + (uint32_t)tid * 16, Lbase + kt + boff_ld);
    };

    int accH[2][4][4], accM[2][4][4], accL[2][4][4];
#pragma unroll
    for (int i = 0; i < 2; i++)
#pragma unroll
        for (int j = 0; j < 4; j++)
#pragma unroll
            for (int q = 0; q < 4; q++) { accH[i][j][q] = 0; accM[i][j][q] = 0; accL[i][j][q] = 0; }

    load_stage(0, 0); cp_commit();
    load_stage(1, 1); cp_commit();

    for (int it = 0; it < NSTAGE_IT; it++) {
        __syncthreads();                          // protect buffer about to be overwritten
        if (it + 2 < NSTAGE_IT) load_stage(it + 2, (it + 2) % 3);
        cp_commit();                              // empty groups at tail keep count aligned
        cp_wait2();                               // stage 'it' resident
        __syncthreads();

        const uint32_t st = sb + (uint32_t)(it % 3) * STAGE_BYTES;
#pragma unroll
        for (int ktl = 0; ktl < 2; ktl++) {
            uint32_t a[2][4];
#pragma unroll
            for (int i = 0; i < 2; i++)
                lds128(a[i], st + SA_OFF +
                       (uint32_t)(ktl * 4096 + (wm * 2 + i) * 512 + lane * 16));
            uint32_t bh[4][2], bm[4][2], bl[4][2];
#pragma unroll
            for (int j = 0; j < 4; j++) {
                uint32_t boff = (uint32_t)(ktl * 2048 + (wn * 4 + j) * 256 + lane * 8);
                lds64(bh[j], st + SBH_OFF + boff);
                lds64(bm[j], st + SBM_OFF + boff);
                lds64(bl[j], st + SBL_OFF + boff);
            }
#pragma unroll
            for (int i = 0; i < 2; i++)
#pragma unroll
                for (int j = 0; j < 4; j++) {
                    mma_s8(accH[i][j], a[i], bh[j][0], bh[j][1]);
                    mma_s8(accM[i][j], a[i], bm[j][0], bm[j][1]);
                    mma_s8(accL[i][j], a[i], bl[j][0], bl[j][1]);
                }
        }
    }

    // Epilogue: u = 65536s*H + 256s*M + s*L (fmaf; each term rounds at its own scale)
    const float s  = __uint_as_float(g_wmax) / QLEV;
    const float sH = s * 65536.0f, sM = s * 256.0f;
    const int row0 = by * 128 + wm * 32 + (lane >> 2);
    const int col0 = bx * 64 + wn * 32 + 2 * (lane & 3);
#pragma unroll
    for (int i = 0; i < 2; i++) {
#pragma unroll
        for (int j = 0; j < 4; j++) {
            float* p0 = g_u1 + (size_t)(row0 + i * 16)     * HID_DIM + col0 + j * 8;
            float* p1 = g_u1 + (size_t)(row0 + i * 16 + 8) * HID_DIM + col0 + j * 8;
            float v0 = fmaf(sH, (float)accH[i][j][0], fmaf(sM, (float)accM[i][j][0], s * (float)accL[i][j][0]));
            float v1 = fmaf(sH, (float)accH[i][j][1], fmaf(sM, (float)accM[i][j][1], s * (float)accL[i][j][1]));
            float v2 = fmaf(sH, (float)accH[i][j][2], fmaf(sM, (float)accM[i][j][2], s * (float)accL[i][j][2]));
            float v3 = fmaf(sH, (float)accH[i][j][3], fmaf(sM, (float)accM[i][j][3], s * (float)accL[i][j][3]));
            *reinterpret_cast<float2*>(p0) = make_float2(v0, v1);
            *reinterpret_cast<float2*>(p1) = make_float2(v2, v3);
        }
    }
}

// ---------------------------------------------------------------------------
// lif1 (float4, 4 chains/thread) + fused rare-spike scatter into U2
// ---------------------------------------------------------------------------
__global__ void lif1_kernel(float* __restrict__ Sdst, const float* __restrict__ W2)
{
    const int t4 = (blockIdx.x * blockDim.x + threadIdx.x) * 4;
    if (t4 >= BATCH * HID_DIM) return;
    const int b  = t4 >> 10;
    const int h0 = t4 & 1023;
    const size_t stride = (size_t)BATCH * HID_DIM;

    float m0 = 0.f, m1 = 0.f, m2 = 0.f, m3 = 0.f;
    for (int t = 0; t < T_STEPS; t++) {
        float4 u = *reinterpret_cast<const float4*>(g_u1 + (size_t)t * stride + t4);
        m0 = m0 * DECAY_F + u.x;  m1 = m1 * DECAY_F + u.y;
        m2 = m2 * DECAY_F + u.z;  m3 = m3 * DECAY_F + u.w;
        float s0 = (m0 >= THRESH_F) ? 1.f : 0.f;
        float s1 = (m1 >= THRESH_F) ? 1.f : 0.f;
        float s2 = (m2 >= THRESH_F) ? 1.f : 0.f;
        float s3 = (m3 >= THRESH_F) ? 1.f : 0.f;
        m0 -= s0 * THRESH_F; m1 -= s1 * THRESH_F;
        m2 -= s2 * THRESH_F; m3 -= s3 * THRESH_F;
        *reinterpret_cast<float4*>(Sdst + (size_t)t * stride + t4) =
            make_float4(s0, s1, s2, s3);
        if (s0 + s1 + s2 + s3 != 0.f) {
            float* u2 = g_u2 + (size_t)t * BATCH * OUT_DIM + (size_t)b * OUT_DIM;
            float sv[4] = {s0, s1, s2, s3};
#pragma unroll
            for (int c = 0; c < 4; c++) {
                if (sv[c] != 0.f) {
                    const float* wr = W2 + (size_t)(h0 + c) * OUT_DIM;
#pragma unroll
                    for (int o = 0; o < OUT_DIM; o++) atomicAdd(u2 + o, wr[o]);
                }
            }
        }
    }
}

// ---------------------------------------------------------------------------
// lif2: smem-staged scan
// ---------------------------------------------------------------------------
__global__ void lif2_kernel(float* __restrict__ Odst)
{
    extern __shared__ float su[];
    const int c0 = blockIdx.x * 256;
    const int tid = threadIdx.x;
    const int NCH = BATCH * OUT_DIM;               // 2560

#pragma unroll 10
    for (int t = 0; t < T_STEPS; t++)
        su[t * 256 + tid] = g_u2[(size_t)t * NCH + c0 + tid];
    __syncthreads();

    float mem = 0.0f;
#pragma unroll 10
    for (int t = 0; t < T_STEPS; t++) {
        float u = su[t * 256 + tid];
        mem = mem * DECAY_F + u;
        float sp = (mem >= THRESH_F) ? 1.0f : 0.0f;
        mem -= sp * THRESH_F;
        Odst[(size_t)t * NCH + c0 + tid] = sp;
    }
}

// ---------------------------------------------------------------------------
// Launch. Order chosen so gemm1 is launch #6 (ncu -s 5 -c 1 captures it).
// ---------------------------------------------------------------------------
extern "C" void kernel_launch(void* const* d_in, const int* in_sizes, int n_in,
                              void* d_out, int out_size)
{
    const float* X  = (const float*)d_in[0];
    const float* W1 = (const float*)d_in[1];
    const float* W2 = (const float*)d_in[2];
    float* out = (float*)d_out;

    const long long TBH = (long long)T_STEPS * BATCH * HID_DIM;
    const long long TBO = (long long)T_STEPS * BATCH * OUT_DIM;

    float* hid_dst;
    float* out_dst;
    if ((long long)out_size == TBH + TBO) {
        hid_dst = out; out_dst = out + TBH;
    } else if ((long long)out_size == TBO) {
        void* p = nullptr; cudaGetSymbolAddress(&p, g_s1);
        hid_dst = (float*)p; out_dst = out;
    } else {
        hid_dst = out;
        void* p = nullptr; cudaGetSymbolAddress(&p, g_s1);
        out_dst = (float*)p;
    }

    cudaFuncSetAttribute(gemm1_i8_kernel,
                         cudaFuncAttributeMaxDynamicSharedMemorySize, SMEM_GEMM);
    cudaFuncSetAttribute(lif2_kernel,
                         cudaFuncAttributeMaxDynamicSharedMemorySize, 256 * T_STEPS * 4);

    // 1) pack X
    {
        int n = KT_TILES * MT_TILES * 32;
        conv_x_kernel<<<(n + 255) / 256, 256>>>(X);
    }
    // 2) zero first half of u2 + wmax init
    zero_a_kernel<<<(U2Q / 2 + 255) / 256, 256>>>();
    // 3) wmax
    wmax_kernel<<<296, 256>>>(W1);
    // 4) quantize W into 3 digit planes
    {
        int n = KT_TILES * NT_TILES * 32;
        conv_w_kernel<<<(n + 255) / 256, 256>>>(W1);
    }
    // 5) zero second half of u2
    zero_b_kernel<<<(U2Q - U2Q / 2 + 255) / 256, 256>>>();
    // 6) GEMM (ncu capture slot)
    {
        dim3 grid(HID_DIM / 64, M_ROWS / 128);    // (16, 200)
        gemm1_i8_kernel<<<grid, 256, SMEM_GEMM>>>();
    }
    // 7) hidden LIF scan + spike scatter
    lif1_kernel<<<BATCH * HID_DIM / 4 / 256, 256>>>(hid_dst, W2);
    // 8) output LIF scan
    lif2_kernel<<<BATCH * OUT_DIM / 256, 256, 256 * T_STEPS * 4>>>(out_dst);
}

// round 14
// speedup vs baseline: 3.2903x; 3.2903x over previous
#include <cuda_runtime.h>
#include <cuda_bf16.h>
#include <cstdint>

// ---------------------------------------------------------------------------
// SNN MLP forward — bf16 HMMA edition, fragment-prepacked (sm_80-era PTX only).
//   Xb  = bf16(X)    binary -> exact, prepacked in m16n8k16 A-fragment order
//   W1  = W1hi+W1lo  bf16 split (validated R4), prepacked in B-fragment order
//   U1  = Xb@W1hi + Xb@W1lo   mma.sync.m16n8k16 bf16, shared fp32 accumulators
//   S1  = LIF-scan(U1) + fused rare-spike scatter into U2 (replaces gemm2)
//   S2  = LIF-scan(U2) smem-staged
// Facts learned: tcgen05 blocked (ptxas target compute_103); s8 mma.sync is
// ALU-emulated (~130 Tops). bf16 HMMA is the real engine (~357 TF/s in R4).
// ---------------------------------------------------------------------------

#define T_STEPS  100
#define BATCH    256
#define IN_DIM   784
#define HID_DIM  1024
#define OUT_DIM  10
#define M_ROWS   25600
#define KP       800                 // 50 k16-tiles (784 = 49 exact + 1 zero)
#define KT_TILES 50
#define MT_TILES 1600                // M_ROWS/16
#define NT_TILES 128                 // HID_DIM/8
#define DECAY_F  0.6f
#define THRESH_F 0.9f

// GEMM tiling: BM=128, BN=256, BK=32 (2 k16/stage), 3 stages, 256 thr
// 8 warps as 2m x 4n, warp tile 64x64.
#define NIT      25                  // 800/32
#define SA_OFF   0                   // A: 2 ktl x 8 mt x 512B = 8KB
#define SBH_OFF  8192                // Bh: 2 ktl x 32 nt x 256B = 16KB
#define SBL_OFF  24576               // Bl: 16KB
#define STAGE_BYTES 40960
#define SMEM_GEMM (3 * STAGE_BYTES)  // 122880

// Device scratch
__device__ float g_u1[(size_t)M_ROWS * HID_DIM];      // 104 MB
__device__ float g_u2[(size_t)M_ROWS * OUT_DIM];      //   1 MB
__device__ float g_s1[(size_t)M_ROWS * HID_DIM];      // fallback hidden store
__device__ __align__(16) uint8_t g_xa[(size_t)KT_TILES * MT_TILES * 512];  // 41 MB bf16 A-frags
__device__ __align__(16) uint8_t g_wh[(size_t)KT_TILES * NT_TILES * 256];  // 3.2 MB B-frags hi
__device__ __align__(16) uint8_t g_wl[(size_t)KT_TILES * NT_TILES * 256];  // 3.2 MB B-frags lo

// ---------------------------------------------------------------------------
// PTX helpers (sm_80-era only)
// ---------------------------------------------------------------------------
__device__ __forceinline__ uint32_t smem_u32(const void* p) {
    uint32_t a;
    asm("{ .reg .u64 t; cvta.to.shared.u64 t, %1; cvt.u32.u64 %0, t; }" : "=r"(a) : "l"(p));
    return a;
}
__device__ __forceinline__ void cp16(uint32_t dst, const void* src) {
    asm volatile("cp.async.cg.shared.global [%0], [%1], 16;" :: "r"(dst), "l"(src));
}
__device__ __forceinline__ void cp_commit() { asm volatile("cp.async.commit_group;" ::: "memory"); }
__device__ __forceinline__ void cp_wait2()  { asm volatile("cp.async.wait_group 2;"  ::: "memory"); }

__device__ __forceinline__ void lds128(uint32_t* r, uint32_t a) {
    asm volatile("ld.shared.v4.u32 {%0,%1,%2,%3}, [%4];"
                 : "=r"(r[0]), "=r"(r[1]), "=r"(r[2]), "=r"(r[3]) : "r"(a));
}
__device__ __forceinline__ void lds64(uint32_t* r, uint32_t a) {
    asm volatile("ld.shared.v2.u32 {%0,%1}, [%2];" : "=r"(r[0]), "=r"(r[1]) : "r"(a));
}
__device__ __forceinline__ void mma_bf16(float* c, const uint32_t* a, uint32_t b0, uint32_t b1) {
    asm volatile("mma.sync.aligned.m16n8k16.row.col.f32.bf16.bf16.f32 "
                 "{%0,%1,%2,%3}, {%4,%5,%6,%7}, {%8,%9}, {%0,%1,%2,%3};"
                 : "+f"(c[0]), "+f"(c[1]), "+f"(c[2]), "+f"(c[3])
                 : "r"(a[0]), "r"(a[1]), "r"(a[2]), "r"(a[3]), "r"(b0), "r"(b1));
}
__device__ __forceinline__ uint32_t bf16x2(float x, float y) {
    __nv_bfloat162 v = __float22bfloat162_rn(make_float2(x, y));
    return *reinterpret_cast<uint32_t*>(&v);
}

// ---------------------------------------------------------------------------
// conv_x: X fp32 [25600,784] -> g_xa bf16 A-fragments.
// Tile (kt, mt): 512B, lane l holds 16B = {a0,a1,a2,a3}:
//   a0:(r, c..c+1)  a1:(r+8, c..c+1)  a2:(r, c+8..9)  a3:(r+8, c+8..9)
//   r = mt*16 + (l>>2), c = kt*16 + 2*(l&3).   kt=49 -> all zero (c>=784).
// ---------------------------------------------------------------------------
__device__ __forceinline__ uint32_t xpair(const float* X, int r, int c) {
    if (c >= IN_DIM) return 0u;
    float2 v = *reinterpret_cast<const float2*>(X + (size_t)r * IN_DIM + c);
    return bf16x2(v.x, v.y);
}

__global__ void conv_x_kernel(const float* __restrict__ X)
{
    int t = blockIdx.x * blockDim.x + threadIdx.x;
    if (t >= KT_TILES * MT_TILES * 32) return;
    int lane = t & 31;
    int tile = t >> 5;
    int kt = tile / MT_TILES;
    int mt = tile - kt * MT_TILES;

    int r = mt * 16 + (lane >> 2);
    int c = kt * 16 + 2 * (lane & 3);

    uint4 frag;
    frag.x = xpair(X, r,     c);
    frag.y = xpair(X, r + 8, c);
    frag.z = xpair(X, r,     c + 8);
    frag.w = xpair(X, r + 8, c + 8);
    *reinterpret_cast<uint4*>(&g_xa[(size_t)t * 16]) = frag;
}

// ---------------------------------------------------------------------------
// zero u2
// ---------------------------------------------------------------------------
__global__ void zero_kernel()
{
    int idx = blockIdx.x * blockDim.x + threadIdx.x;
    if (idx < M_ROWS * OUT_DIM / 4)
        reinterpret_cast<float4*>(g_u2)[idx] = make_float4(0.f, 0.f, 0.f, 0.f);
}

// ---------------------------------------------------------------------------
// conv_w: W1 fp32 [784,1024] -> hi/lo bf16 B-fragments.
// Tile (kt, nt): 256B, lane l holds 8B = {b0,b1}:
//   b0:(k..k+1, n)  b1:(k+8..9, n),  n = nt*8+(l>>2), k = kt*16+2*(l&3)
// ---------------------------------------------------------------------------
__global__ void conv_w_kernel(const float* __restrict__ W1)
{
    int t = blockIdx.x * blockDim.x + threadIdx.x;
    if (t >= KT_TILES * NT_TILES * 32) return;
    int lane = t & 31;
    int tile = t >> 5;
    int kt = tile >> 7;
    int nt = tile & 127;

    int n = nt * 8 + (lane >> 2);
    int k = kt * 16 + 2 * (lane & 3);

    float w[4];
#pragma unroll
    for (int j = 0; j < 4; j++) {
        int kk = k + (j >> 1) * 8 + (j & 1);          // k, k+1, k+8, k+9
        w[j] = (kk < IN_DIM) ? W1[(size_t)kk * HID_DIM + n] : 0.f;
    }
    float hi[4], lo[4];
#pragma unroll
    for (int j = 0; j < 4; j++) {
        hi[j] = __bfloat162float(__float2bfloat16_rn(w[j]));
        lo[j] = w[j] - hi[j];
    }
    *reinterpret_cast<uint2*>(&g_wh[(size_t)t * 8]) =
        make_uint2(bf16x2(hi[0], hi[1]), bf16x2(hi[2], hi[3]));
    *reinterpret_cast<uint2*>(&g_wl[(size_t)t * 8]) =
        make_uint2(bf16x2(lo[0], lo[1]), bf16x2(lo[2], lo[3]));
}

// ---------------------------------------------------------------------------
// GEMM1: U1 = Xb@(W1hi + W1lo), shared fp32 accumulators (R4 numerics).
// 256 thr / 8 warps (2m x 4n), warp 64x64; BM=128 BN=256 BK=32; 3 stages.
// Prepacked operands -> linear cp.async, conflict-free lds128/lds64, no ldmatrix.
// ---------------------------------------------------------------------------
__global__ void __launch_bounds__(256, 1)
gemm1_kernel()
{
    extern __shared__ char smem[];
    const uint32_t sb = smem_u32(smem);
    const int tid  = threadIdx.x;
    const int lane = tid & 31;
    const int w    = tid >> 5;
    const int wm   = w >> 2;           // 0..1
    const int wn   = w & 3;            // 0..3
    const int bx   = blockIdx.x;       // 0..3   (N tiles of 256)
    const int by   = blockIdx.y;       // 0..199 (M tiles of 128)

    // stage loaders (all linear)
    auto load_stage = [&](int it, int s) {
        uint32_t st = sb + (uint32_t)s * STAGE_BYTES;
        // A: 8KB = 512 cp16; [ktl][mt_local(8)][lane*16]
#pragma unroll
        for (int h = 0; h < 2; h++) {
            int id  = tid + h * 256;               // 0..511
            int ktl = id >> 8;
            int rem = id & 255;                    // mt_local*32 + lane
            cp16(st + SA_OFF + (uint32_t)id * 16,
                 g_xa + ((size_t)(it * 2 + ktl) * MT_TILES + by * 8 + (rem >> 5)) * 512
                      + (rem & 31) * 16);
        }
        // B planes: 16KB each = 1024 cp16; [ktl][nt_local(32)][256B]
#pragma unroll
        for (int h = 0; h < 4; h++) {
            int id  = tid + h * 256;               // 0..1023
            int ktl = id >> 9;
            int rem = id & 511;                    // nt_local*16 + chunk
            size_t src = ((size_t)(it * 2 + ktl) * NT_TILES + bx * 32 + (rem >> 4)) * 256
                         + (rem & 15) * 16;
            uint32_t dst = (uint32_t)(ktl * 8192 + (rem >> 4) * 256 + (rem & 15) * 16);
            cp16(st + SBH_OFF + dst, g_wh + src);
            cp16(st + SBL_OFF + dst, g_wl + src);
        }
    };

    float acc[4][8][4];
#pragma unroll
    for (int i = 0; i < 4; i++)
#pragma unroll
        for (int j = 0; j < 8; j++)
#pragma unroll
            for (int q = 0; q < 4; q++) acc[i][j][q] = 0.f;

    load_stage(0, 0); cp_commit();
    load_stage(1, 1); cp_commit();

    for (int it = 0; it < NIT; it++) {
        __syncthreads();                           // buffer (it%3) about to be reused
        if (it + 2 < NIT) load_stage(it + 2, (it + 2) % 3);
        cp_commit();                               // empty groups at tail keep count aligned
        cp_wait2();                                // stage 'it' resident
        __syncthreads();

        const uint32_t st = sb + (uint32_t)(it % 3) * STAGE_BYTES;
#pragma unroll
        for (int ktl = 0; ktl < 2; ktl++) {
            uint32_t a[4][4];
#pragma unroll
            for (int i = 0; i < 4; i++)
                lds128(a[i], st + SA_OFF +
                       (uint32_t)(ktl * 4096 + (wm * 4 + i) * 512 + lane * 16));
#pragma unroll
            for (int j = 0; j < 8; j++) {          // hi plane
                uint32_t b[2];
                lds64(b, st + SBH_OFF +
                      (uint32_t)(ktl * 8192 + (wn * 8 + j) * 256 + lane * 8));
#pragma unroll
                for (int i = 0; i < 4; i++) mma_bf16(acc[i][j], a[i], b[0], b[1]);
            }
#pragma unroll
            for (int j = 0; j < 8; j++) {          // lo plane, same accumulators
                uint32_t b[2];
                lds64(b, st + SBL_OFF +
                      (uint32_t)(ktl * 8192 + (wn * 8 + j) * 256 + lane * 8));
#pragma unroll
                for (int i = 0; i < 4; i++) mma_bf16(acc[i][j], a[i], b[0], b[1]);
            }
        }
    }

    // Epilogue -> g_u1
    const int row0 = by * 128 + wm * 64 + (lane >> 2);
    const int col0 = bx * 256 + wn * 64 + 2 * (lane & 3);
#pragma unroll
    for (int i = 0; i < 4; i++) {
#pragma unroll
        for (int j = 0; j < 8; j++) {
            float* p0 = g_u1 + (size_t)(row0 + i * 16)     * HID_DIM + col0 + j * 8;
            float* p1 = g_u1 + (size_t)(row0 + i * 16 + 8) * HID_DIM + col0 + j * 8;
            *reinterpret_cast<float2*>(p0) = make_float2(acc[i][j][0], acc[i][j][1]);
            *reinterpret_cast<float2*>(p1) = make_float2(acc[i][j][2], acc[i][j][3]);
        }
    }
}

// ---------------------------------------------------------------------------
// lif1 (float4, 4 chains/thread) + fused rare-spike scatter into U2
// ---------------------------------------------------------------------------
__global__ void lif1_kernel(float* __restrict__ Sdst, const float* __restrict__ W2)
{
    const int t4 = (blockIdx.x * blockDim.x + threadIdx.x) * 4;
    if (t4 >= BATCH * HID_DIM) return;
    const int b  = t4 >> 10;
    const int h0 = t4 & 1023;
    const size_t stride = (size_t)BATCH * HID_DIM;

    float m0 = 0.f, m1 = 0.f, m2 = 0.f, m3 = 0.f;
    for (int t = 0; t < T_STEPS; t++) {
        float4 u = *reinterpret_cast<const float4*>(g_u1 + (size_t)t * stride + t4);
        m0 = m0 * DECAY_F + u.x;  m1 = m1 * DECAY_F + u.y;
        m2 = m2 * DECAY_F + u.z;  m3 = m3 * DECAY_F + u.w;
        float s0 = (m0 >= THRESH_F) ? 1.f : 0.f;
        float s1 = (m1 >= THRESH_F) ? 1.f : 0.f;
        float s2 = (m2 >= THRESH_F) ? 1.f : 0.f;
        float s3 = (m3 >= THRESH_F) ? 1.f : 0.f;
        m0 -= s0 * THRESH_F; m1 -= s1 * THRESH_F;
        m2 -= s2 * THRESH_F; m3 -= s3 * THRESH_F;
        *reinterpret_cast<float4*>(Sdst + (size_t)t * stride + t4) =
            make_float4(s0, s1, s2, s3);
        if (s0 + s1 + s2 + s3 != 0.f) {            // rare path
            float* u2 = g_u2 + (size_t)t * BATCH * OUT_DIM + (size_t)b * OUT_DIM;
            float sv[4] = {s0, s1, s2, s3};
#pragma unroll
            for (int c = 0; c < 4; c++) {
                if (sv[c] != 0.f) {
                    const float* wr = W2 + (size_t)(h0 + c) * OUT_DIM;
#pragma unroll
                    for (int o = 0; o < OUT_DIM; o++) atomicAdd(u2 + o, wr[o]);
                }
            }
        }
    }
}

// ---------------------------------------------------------------------------
// lif2: smem-staged scan
// ---------------------------------------------------------------------------
__global__ void lif2_kernel(float* __restrict__ Odst)
{
    extern __shared__ float su[];
    const int c0 = blockIdx.x * 256;
    const int tid = threadIdx.x;
    const int NCH = BATCH * OUT_DIM;               // 2560

#pragma unroll 10
    for (int t = 0; t < T_STEPS; t++)
        su[t * 256 + tid] = g_u2[(size_t)t * NCH + c0 + tid];
    __syncthreads();

    float mem = 0.0f;
#pragma unroll 10
    for (int t = 0; t < T_STEPS; t++) {
        float u = su[t * 256 + tid];
        mem = mem * DECAY_F + u;
        float sp = (mem >= THRESH_F) ? 1.0f : 0.0f;
        mem -= sp * THRESH_F;
        Odst[(size_t)t * NCH + c0 + tid] = sp;
    }
}

// ---------------------------------------------------------------------------
// Launch. gemm is launch #4 (the slot ncu empirically captures).
// ---------------------------------------------------------------------------
extern "C" void kernel_launch(void* const* d_in, const int* in_sizes, int n_in,
                              void* d_out, int out_size)
{
    const float* X  = (const float*)d_in[0];
    const float* W1 = (const float*)d_in[1];
    const float* W2 = (const float*)d_in[2];
    float* out = (float*)d_out;

    const long long TBH = (long long)T_STEPS * BATCH * HID_DIM;
    const long long TBO = (long long)T_STEPS * BATCH * OUT_DIM;

    float* hid_dst;
    float* out_dst;
    if ((long long)out_size == TBH + TBO) {
        hid_dst = out; out_dst = out + TBH;
    } else if ((long long)out_size == TBO) {
        void* p = nullptr; cudaGetSymbolAddress(&p, g_s1);
        hid_dst = (float*)p; out_dst = out;
    } else {
        hid_dst = out;
        void* p = nullptr; cudaGetSymbolAddress(&p, g_s1);
        out_dst = (float*)p;
    }

    cudaFuncSetAttribute(gemm1_kernel,
                         cudaFuncAttributeMaxDynamicSharedMemorySize, SMEM_GEMM);
    cudaFuncSetAttribute(lif2_kernel,
                         cudaFuncAttributeMaxDynamicSharedMemorySize, 256 * T_STEPS * 4);

    // 1) pack X as A-fragments
    {
        int n = KT_TILES * MT_TILES * 32;                     // 2,560,000
        conv_x_kernel<<<(n + 255) / 256, 256>>>(X);
    }
    // 2) zero u2
    zero_kernel<<<(M_ROWS * OUT_DIM / 4 + 255) / 256, 256>>>();
    // 3) split + pack W as B-fragments
    {
        int n = KT_TILES * NT_TILES * 32;                     // 204,800
        conv_w_kernel<<<(n + 255) / 256, 256>>>(W1);
    }
    // 4) GEMM (ncu capture slot)
    {
        dim3 grid(HID_DIM / 256, M_ROWS / 128);               // (4, 200)
        gemm1_kernel<<<grid, 256, SMEM_GEMM>>>();
    }
    // 5) hidden LIF scan + fused spike scatter
    lif1_kernel<<<BATCH * HID_DIM / 4 / 256, 256>>>(hid_dst, W2);
    // 6) output LIF scan
    lif2_kernel<<<BATCH * OUT_DIM / 256, 256, 256 * T_STEPS * 4>>>(out_dst);
}